// round 1
// baseline (speedup 1.0000x reference)
#include <cuda_runtime.h>

#define VOCAB 32
#define UTT_LEN 16
#define NTYPES 5
#define MPT 10
#define SUPPORT 100000
#define BATCH 2048

#define NS 16                            // support chunks
#define CHUNK (SUPPORT / NS)             // 6250
#define TPB 256
#define FULL_ITERS (CHUNK / TPB)         // 24
#define TAIL (CHUNK - FULL_ITERS * TPB)  // 106
#define NGROUPS (BATCH / 32)             // 64

// scratch (no cudaMalloc allowed)
__device__ unsigned char g_packed[SUPPORT * UTT_LEN]; // token*4 per position
__device__ unsigned int  g_keys[BATCH];               // (cnt<<17)|(131071-row)
__device__ int g_u64, g_m64;                          // dtype flags

// ---------------------------------------------------------------------------
// Kernel 0: detect whether int inputs are 64-bit or 32-bit.
// Values are small non-negative ints; if stored as int64 (little-endian),
// every odd 32-bit word of the first 128 pairs is 0. P(false positive for
// int32 data) ~ 32^-128.
// ---------------------------------------------------------------------------
__global__ void detect_kernel(const int* __restrict__ utts32,
                              const int* __restrict__ mean32) {
    int lane = threadIdx.x;
    bool unz = false, mnz = false;
    for (int i = lane; i < 128; i += 32) {
        unz |= (utts32[2 * i + 1] != 0);
        mnz |= (mean32[2 * i + 1] != 0);
    }
    unsigned ub = __ballot_sync(0xffffffffu, unz);
    unsigned mb = __ballot_sync(0xffffffffu, mnz);
    if (lane == 0) { g_u64 = (ub == 0); g_m64 = (mb == 0); }
}

// ---------------------------------------------------------------------------
// Kernel 1: decode one-hot support rows -> packed tokens (pre-scaled by 4 so
// they are direct byte offsets into the 128B-per-position shared table).
// Also zeroes the key scratch each launch (graph-replay safe).
// One thread per (row, position): reads 32 consecutive floats (128B = 1 line).
// ---------------------------------------------------------------------------
__global__ void decode_kernel(const float* __restrict__ support) {
    unsigned tid = blockIdx.x * blockDim.x + threadIdx.x;
    if (tid < BATCH) g_keys[tid] = 0u;
    if (tid >= SUPPORT * UTT_LEN) return;
    const float4* p = reinterpret_cast<const float4*>(support + (size_t)tid * VOCAB);
    int t = 0;
#pragma unroll
    for (int j = 0; j < 8; j++) {
        float4 v = p[j];
        if (v.x != 0.0f) t = 4 * j + 0;
        if (v.y != 0.0f) t = 4 * j + 1;
        if (v.z != 0.0f) t = 4 * j + 2;
        if (v.w != 0.0f) t = 4 * j + 3;
    }
    g_packed[tid] = (unsigned char)(t << 2);
}

// ---------------------------------------------------------------------------
// Kernel 2: bit-sliced match counting + argmax.
// grid = (NS chunks, 64 query-groups), block = 256 threads.
// Each thread scans rows {chunkBase + tid + 256*i} and maintains, bit-sliced
// across its group's 32 queries:
//   mx[5]  : best match count (0..16)
//   bi[13] : local row (tid:8 bits | iter:5 bits) achieving it (first tie kept)
// ---------------------------------------------------------------------------
__device__ __forceinline__ void fa(unsigned a, unsigned b, unsigned c,
                                   unsigned& s, unsigned& cy) {
    s  = a ^ b ^ c;                       // LOP3 0x96
    cy = (a & b) | (a & c) | (b & c);     // LOP3 0xE8 (majority)
}
__device__ __forceinline__ void ha(unsigned a, unsigned b,
                                   unsigned& s, unsigned& cy) {
    s = a ^ b; cy = a & b;
}

__global__ void __launch_bounds__(TPB) knn_kernel(const void* __restrict__ uttsv) {
    __shared__ unsigned tbl[UTT_LEN * VOCAB];  // tbl[m*32+v]: bit q = (query q tok[m]==v)

    const unsigned tid   = threadIdx.x;
    const unsigned lane  = tid & 31;
    const unsigned chunk = blockIdx.x;
    const unsigned group = blockIdx.y;

    // Build query mask table with warp 0 via ballots.
    if (tid < 32) {
        const int is64 = g_u64;
        const unsigned col = group * 32 + lane;
        const long long* u64p = (const long long*)uttsv;
        const int*       u32p = (const int*)uttsv;
#pragma unroll
        for (int m = 0; m < UTT_LEN; m++) {
            int tok = is64 ? (int)u64p[(size_t)m * BATCH + col]
                           : u32p[(size_t)m * BATCH + col];
#pragma unroll
            for (int v = 0; v < VOCAB; v++) {
                unsigned bm = __ballot_sync(0xffffffffu, tok == v);
                if (lane == (unsigned)v) tbl[m * VOCAB + v] = bm;
            }
        }
    }
    __syncthreads();

    const unsigned rowBase = chunk * CHUNK;
    const uint4* pk = reinterpret_cast<const uint4*>(g_packed) + rowBase + tid;

    unsigned mx[5] = {0u, 0u, 0u, 0u, 0u};
    unsigned tb[8];
#pragma unroll
    for (int p = 0; p < 8; p++) tb[p] = (tid & (1u << p)) ? 0xffffffffu : 0u;
    unsigned bi[13];
#pragma unroll
    for (int p = 0; p < 8; p++) bi[p] = tb[p];   // init: row = tid (iter 0)
#pragma unroll
    for (int p = 8; p < 13; p++) bi[p] = 0u;

    const char* tbc = (const char*)tbl;

    auto body = [&](int i) {
        uint4 pw = pk[i * TPB];
        unsigned l[16];
        // extract byte (t*4) with PRMT, direct LDS at [byte + m*128]
        l[0]  = *(const unsigned*)(tbc + 0 * 128  + __byte_perm(pw.x, 0, 0x4440));
        l[1]  = *(const unsigned*)(tbc + 1 * 128  + __byte_perm(pw.x, 0, 0x4441));
        l[2]  = *(const unsigned*)(tbc + 2 * 128  + __byte_perm(pw.x, 0, 0x4442));
        l[3]  = *(const unsigned*)(tbc + 3 * 128  + __byte_perm(pw.x, 0, 0x4443));
        l[4]  = *(const unsigned*)(tbc + 4 * 128  + __byte_perm(pw.y, 0, 0x4440));
        l[5]  = *(const unsigned*)(tbc + 5 * 128  + __byte_perm(pw.y, 0, 0x4441));
        l[6]  = *(const unsigned*)(tbc + 6 * 128  + __byte_perm(pw.y, 0, 0x4442));
        l[7]  = *(const unsigned*)(tbc + 7 * 128  + __byte_perm(pw.y, 0, 0x4443));
        l[8]  = *(const unsigned*)(tbc + 8 * 128  + __byte_perm(pw.z, 0, 0x4440));
        l[9]  = *(const unsigned*)(tbc + 9 * 128  + __byte_perm(pw.z, 0, 0x4441));
        l[10] = *(const unsigned*)(tbc + 10 * 128 + __byte_perm(pw.z, 0, 0x4442));
        l[11] = *(const unsigned*)(tbc + 11 * 128 + __byte_perm(pw.z, 0, 0x4443));
        l[12] = *(const unsigned*)(tbc + 12 * 128 + __byte_perm(pw.w, 0, 0x4440));
        l[13] = *(const unsigned*)(tbc + 13 * 128 + __byte_perm(pw.w, 0, 0x4441));
        l[14] = *(const unsigned*)(tbc + 14 * 128 + __byte_perm(pw.w, 0, 0x4442));
        l[15] = *(const unsigned*)(tbc + 15 * 128 + __byte_perm(pw.w, 0, 0x4443));

        // CSA tree: 16 one-bit planes -> 5-bit count planes n0..n4 (30 LOP3)
        unsigned s0, c0, s1, c1, s2, c2, s3, c3, s4, c4;
        fa(l[0], l[1], l[2], s0, c0);
        fa(l[3], l[4], l[5], s1, c1);
        fa(l[6], l[7], l[8], s2, c2);
        fa(l[9], l[10], l[11], s3, c3);
        fa(l[12], l[13], l[14], s4, c4);
        unsigned t0, d0, t1, d1;
        fa(s0, s1, s2, t0, d0);
        fa(s3, s4, l[15], t1, d1);
        unsigned n0, e0; ha(t0, t1, n0, e0);
        unsigned f0, g0, f1, g1, f2, g2;
        fa(c0, c1, c2, f0, g0);
        fa(c3, c4, d0, f1, g1);
        fa(f0, f1, d1, f2, g2);
        unsigned n1, g3; ha(f2, e0, n1, g3);
        unsigned h0, k0; fa(g0, g1, g2, h0, k0);
        unsigned n2, k1; ha(h0, g3, n2, k1);
        unsigned n3, n4; ha(k0, k1, n3, n4);

        // strict greater-than vs running max (bit q), LSB->MSB chain
        unsigned gt;
        gt = n0 & ~mx[0];
        gt = (n1 & ~mx[1]) | (~(n1 ^ mx[1]) & gt);
        gt = (n2 & ~mx[2]) | (~(n2 ^ mx[2]) & gt);
        gt = (n3 & ~mx[3]) | (~(n3 ^ mx[3]) & gt);
        gt = (n4 & ~mx[4]) | (~(n4 ^ mx[4]) & gt);

        if (gt) {  // rare after warmup
            unsigned ng = ~gt;
            mx[0] = (n0 & gt) | (mx[0] & ng);
            mx[1] = (n1 & gt) | (mx[1] & ng);
            mx[2] = (n2 & gt) | (mx[2] & ng);
            mx[3] = (n3 & gt) | (mx[3] & ng);
            mx[4] = (n4 & gt) | (mx[4] & ng);
#pragma unroll
            for (int p = 0; p < 8; p++) bi[p] = (tb[p] & gt) | (bi[p] & ng);
#pragma unroll
            for (int p = 0; p < 5; p++) {
                unsigned ib = (unsigned)(-(int)((i >> p) & 1));
                bi[8 + p] = (ib & gt) | (bi[8 + p] & ng);
            }
        }
    };

#pragma unroll 4
    for (int i = 0; i < FULL_ITERS; i++) body(i);
    if (tid < TAIL) body(FULL_ITERS);

    // Warp butterfly merge of (cnt desc, row asc), all in bit-sliced domain.
#pragma unroll
    for (int k = 1; k < 32; k <<= 1) {
        unsigned o[5], q[13];
#pragma unroll
        for (int p = 0; p < 5; p++)  o[p] = __shfl_xor_sync(0xffffffffu, mx[p], k);
#pragma unroll
        for (int p = 0; p < 13; p++) q[p] = __shfl_xor_sync(0xffffffffu, bi[p], k);
        unsigned gtc = mx[0] & ~o[0];
#pragma unroll
        for (int p = 1; p < 5; p++)
            gtc = (mx[p] & ~o[p]) | (~(mx[p] ^ o[p]) & gtc);
        unsigned orx = 0;
#pragma unroll
        for (int p = 0; p < 5; p++) orx |= mx[p] ^ o[p];   // ~orx = counts equal
        unsigned lt = ~bi[0] & q[0];
#pragma unroll
        for (int p = 1; p < 13; p++)
            lt = (~bi[p] & q[p]) | (~(bi[p] ^ q[p]) & lt);  // my row < partner row
        unsigned tm = gtc | (lt & ~orx);                    // keep mine
        unsigned nt = ~tm;
#pragma unroll
        for (int p = 0; p < 5; p++)  mx[p] = (mx[p] & tm) | (o[p] & nt);
#pragma unroll
        for (int p = 0; p < 13; p++) bi[p] = (bi[p] & tm) | (q[p] & nt);
    }

    // lane q extracts query q's (cnt,row) from the merged planes
    unsigned cnt = 0, lr = 0;
#pragma unroll
    for (int p = 0; p < 5; p++)  cnt |= ((mx[p] >> lane) & 1u) << p;
#pragma unroll
    for (int p = 0; p < 13; p++) lr  |= ((bi[p] >> lane) & 1u) << p;
    unsigned row = rowBase + lr;
    unsigned key = (cnt << 17) | (131071u - row);
    atomicMax(&g_keys[group * 32 + lane], key);
}

// ---------------------------------------------------------------------------
// Kernel 3: gather meanings of the winner and emit one-hot output.
// Writes ALL out elements (d_out is poisoned).
// ---------------------------------------------------------------------------
__global__ void out_kernel(const void* __restrict__ meanv, float* __restrict__ out) {
    int idx = blockIdx.x * blockDim.x + threadIdx.x;
    if (idx >= BATCH * NTYPES * MPT) return;
    int n = idx / (NTYPES * MPT);
    int r = idx % (NTYPES * MPT);
    int t = r / MPT;
    int c = r % MPT;
    unsigned key = g_keys[n];
    int row = 131071 - (int)(key & 0x1FFFFu);
    long long mval = g_m64 ? ((const long long*)meanv)[(size_t)row * NTYPES + t]
                           : (long long)((const int*)meanv)[(size_t)row * NTYPES + t];
    out[idx] = (mval == (long long)c) ? 1.0f : 0.0f;
}

extern "C" void kernel_launch(void* const* d_in, const int* in_sizes, int n_in,
                              void* d_out, int out_size) {
    const void*  utts     = d_in[0];                 // [16,2048] int64/int32
    const float* support  = (const float*)d_in[1];   // [100000,512] fp32 one-hot
    const void*  meanings = d_in[2];                 // [100000,5] int64/int32
    float* out = (float*)d_out;                      // [2048,5,10] fp32

    detect_kernel<<<1, 32>>>((const int*)utts, (const int*)meanings);
    decode_kernel<<<(SUPPORT * UTT_LEN + 255) / 256, 256>>>(support);
    dim3 grid(NS, NGROUPS);
    knn_kernel<<<grid, TPB>>>(utts);
    out_kernel<<<(BATCH * NTYPES * MPT + 255) / 256, 256>>>(meanings, out);
}

// round 2
// speedup vs baseline: 1.5712x; 1.5712x over previous
#include <cuda_runtime.h>

#define VOCAB 32
#define UTT_LEN 16
#define NTYPES 5
#define MPT 10
#define SUPPORT 100000
#define BATCH 2048

#define NS 16                            // support chunks
#define CHUNK (SUPPORT / NS)             // 6250
#define TPB 256
#define FULL_ITERS (CHUNK / TPB)         // 24
#define TAIL (CHUNK - FULL_ITERS * TPB)  // 106
#define NGROUPS (BATCH / 32)             // 64

// scratch (no cudaMalloc allowed)
__device__ unsigned char g_packed[SUPPORT * UTT_LEN]; // token*4 per position
__device__ unsigned int  g_keys[BATCH];               // (cnt<<17)|(131071-row)
__device__ int g_u64, g_m64;                          // dtype flags

// ---------------------------------------------------------------------------
// Kernel 1 (fused): detect int width + zero keys + decode one-hot support
// rows -> packed tokens (pre-scaled by 4 = byte offsets into the 128B/pos
// shared table). One thread per (row, position): 32 consecutive floats.
// ---------------------------------------------------------------------------
__global__ void decode_kernel(const float* __restrict__ support,
                              const int* __restrict__ utts32,
                              const int* __restrict__ mean32) {
    unsigned tid = blockIdx.x * blockDim.x + threadIdx.x;

    // fused dtype detection (block 0, warp 0). Values are small non-negative
    // ints; if int64 (LE), every odd 32-bit word of the first 128 pairs is 0.
    if (tid < 32) {
        bool unz = false, mnz = false;
        for (int i = tid; i < 128; i += 32) {
            unz |= (utts32[2 * i + 1] != 0);
            mnz |= (mean32[2 * i + 1] != 0);
        }
        unsigned ub = __ballot_sync(0xffffffffu, unz);
        unsigned mb = __ballot_sync(0xffffffffu, mnz);
        if (tid == 0) { g_u64 = (ub == 0); g_m64 = (mb == 0); }
    }
    if (tid < BATCH) g_keys[tid] = 0u;
    if (tid >= SUPPORT * UTT_LEN) return;

    const float4* p = reinterpret_cast<const float4*>(support + (size_t)tid * VOCAB);
    int t = 0;
#pragma unroll
    for (int j = 0; j < 8; j++) {
        float4 v = __ldcs(p + j);        // streaming: no reuse, keep L2 clean
        if (v.x != 0.0f) t = 4 * j + 0;
        if (v.y != 0.0f) t = 4 * j + 1;
        if (v.z != 0.0f) t = 4 * j + 2;
        if (v.w != 0.0f) t = 4 * j + 3;
    }
    g_packed[tid] = (unsigned char)(t << 2);
}

// ---------------------------------------------------------------------------
// Kernel 2: bit-sliced match counting + argmax.
// grid = (NS chunks, 64 query-groups), block = 256 threads.
// Per thread, bit-sliced across its group's 32 queries:
//   mx0..4 : best match count (0..16)
//   b0..4  : iteration index (5 bits) achieving it; tid bits are implicit.
// Fully unrolled so iteration-bit plane updates are single LOP3 w/ immediates.
// ---------------------------------------------------------------------------
__device__ __forceinline__ void fa(unsigned a, unsigned b, unsigned c,
                                   unsigned& s, unsigned& cy) {
    s  = a ^ b ^ c;                       // LOP3 0x96
    cy = (a & b) | (a & c) | (b & c);     // LOP3 0xE8
}
__device__ __forceinline__ void ha(unsigned a, unsigned b,
                                   unsigned& s, unsigned& cy) {
    s = a ^ b; cy = a & b;
}

__global__ void __launch_bounds__(TPB) knn_kernel(const void* __restrict__ uttsv) {
    __shared__ unsigned tbl[UTT_LEN * VOCAB];  // tbl[m*32+v]: bit q = (query q tok[m]==v)

    const unsigned tid   = threadIdx.x;
    const unsigned lane  = tid & 31;
    const unsigned warp  = tid >> 5;
    const unsigned chunk = blockIdx.x;
    const unsigned group = blockIdx.y;

    // Parallel table build: each of the 8 warps handles 2 positions.
    {
        const int is64 = g_u64;
        const unsigned col = group * 32 + lane;
        const long long* u64p = (const long long*)uttsv;
        const int*       u32p = (const int*)uttsv;
#pragma unroll
        for (int mm = 0; mm < 2; mm++) {
            int m = (int)(warp * 2 + mm);
            int tok = is64 ? (int)u64p[(size_t)m * BATCH + col]
                           : u32p[(size_t)m * BATCH + col];
#pragma unroll
            for (int v = 0; v < VOCAB; v++) {
                unsigned bm = __ballot_sync(0xffffffffu, tok == v);
                if (lane == (unsigned)v) tbl[m * VOCAB + v] = bm;
            }
        }
    }
    __syncthreads();

    const unsigned rowBase = chunk * CHUNK;
    const uint4* pk = reinterpret_cast<const uint4*>(g_packed) + rowBase + tid;
    const char* tbc = (const char*)tbl;

    unsigned mx0 = 0, mx1 = 0, mx2 = 0, mx3 = 0, mx4 = 0;
    unsigned b0 = 0, b1 = 0, b2 = 0, b3 = 0, b4 = 0;

#define STEP(I)                                                                   \
    do {                                                                          \
        uint4 pw = pk[(I) * TPB];                                                 \
        unsigned l0  = *(const unsigned*)(tbc + 0 * 128  + __byte_perm(pw.x, 0, 0x4440)); \
        unsigned l1  = *(const unsigned*)(tbc + 1 * 128  + __byte_perm(pw.x, 0, 0x4441)); \
        unsigned l2  = *(const unsigned*)(tbc + 2 * 128  + __byte_perm(pw.x, 0, 0x4442)); \
        unsigned l3  = *(const unsigned*)(tbc + 3 * 128  + __byte_perm(pw.x, 0, 0x4443)); \
        unsigned l4  = *(const unsigned*)(tbc + 4 * 128  + __byte_perm(pw.y, 0, 0x4440)); \
        unsigned l5  = *(const unsigned*)(tbc + 5 * 128  + __byte_perm(pw.y, 0, 0x4441)); \
        unsigned l6  = *(const unsigned*)(tbc + 6 * 128  + __byte_perm(pw.y, 0, 0x4442)); \
        unsigned l7  = *(const unsigned*)(tbc + 7 * 128  + __byte_perm(pw.y, 0, 0x4443)); \
        unsigned l8  = *(const unsigned*)(tbc + 8 * 128  + __byte_perm(pw.z, 0, 0x4440)); \
        unsigned l9  = *(const unsigned*)(tbc + 9 * 128  + __byte_perm(pw.z, 0, 0x4441)); \
        unsigned l10 = *(const unsigned*)(tbc + 10 * 128 + __byte_perm(pw.z, 0, 0x4442)); \
        unsigned l11 = *(const unsigned*)(tbc + 11 * 128 + __byte_perm(pw.z, 0, 0x4443)); \
        unsigned l12 = *(const unsigned*)(tbc + 12 * 128 + __byte_perm(pw.w, 0, 0x4440)); \
        unsigned l13 = *(const unsigned*)(tbc + 13 * 128 + __byte_perm(pw.w, 0, 0x4441)); \
        unsigned l14 = *(const unsigned*)(tbc + 14 * 128 + __byte_perm(pw.w, 0, 0x4442)); \
        unsigned l15 = *(const unsigned*)(tbc + 15 * 128 + __byte_perm(pw.w, 0, 0x4443)); \
        unsigned s0, c0, s1, c1, s2, c2, s3, c3, s4, c4;                          \
        fa(l0, l1, l2, s0, c0);                                                   \
        fa(l3, l4, l5, s1, c1);                                                   \
        fa(l6, l7, l8, s2, c2);                                                   \
        fa(l9, l10, l11, s3, c3);                                                 \
        fa(l12, l13, l14, s4, c4);                                                \
        unsigned t0, d0, t1, d1;                                                  \
        fa(s0, s1, s2, t0, d0);                                                   \
        fa(s3, s4, l15, t1, d1);                                                  \
        unsigned n0, e0; ha(t0, t1, n0, e0);                                      \
        unsigned f0, g0, f1, g1, f2, g2;                                          \
        fa(c0, c1, c2, f0, g0);                                                   \
        fa(c3, c4, d0, f1, g1);                                                   \
        fa(f0, f1, d1, f2, g2);                                                   \
        unsigned n1, g3; ha(f2, e0, n1, g3);                                      \
        unsigned h0, k0; fa(g0, g1, g2, h0, k0);                                  \
        unsigned n2, k1; ha(h0, g3, n2, k1);                                      \
        unsigned n3, n4; ha(k0, k1, n3, n4);                                      \
        unsigned gt = n0 & ~mx0;                                                  \
        gt = (n1 & ~mx1) | (~(n1 ^ mx1) & gt);                                    \
        gt = (n2 & ~mx2) | (~(n2 ^ mx2) & gt);                                    \
        gt = (n3 & ~mx3) | (~(n3 ^ mx3) & gt);                                    \
        gt = (n4 & ~mx4) | (~(n4 ^ mx4) & gt);                                    \
        mx0 = (n0 & gt) | (mx0 & ~gt);                                            \
        mx1 = (n1 & gt) | (mx1 & ~gt);                                            \
        mx2 = (n2 & gt) | (mx2 & ~gt);                                            \
        mx3 = (n3 & gt) | (mx3 & ~gt);                                            \
        mx4 = (n4 & gt) | (mx4 & ~gt);                                            \
        if ((I) & 1)  b0 |= gt; else b0 &= ~gt;                                   \
        if ((I) & 2)  b1 |= gt; else b1 &= ~gt;                                   \
        if ((I) & 4)  b2 |= gt; else b2 &= ~gt;                                   \
        if ((I) & 8)  b3 |= gt; else b3 &= ~gt;                                   \
        if ((I) & 16) b4 |= gt; else b4 &= ~gt;                                   \
    } while (0)

    STEP(0);  STEP(1);  STEP(2);  STEP(3);  STEP(4);  STEP(5);
    STEP(6);  STEP(7);  STEP(8);  STEP(9);  STEP(10); STEP(11);
    STEP(12); STEP(13); STEP(14); STEP(15); STEP(16); STEP(17);
    STEP(18); STEP(19); STEP(20); STEP(21); STEP(22); STEP(23);
    if (tid < TAIL) STEP(24);
#undef STEP

    // Materialize full row planes: row = tid (8 bits) | iter (5 bits).
    unsigned mx[5] = {mx0, mx1, mx2, mx3, mx4};
    unsigned bi[13];
#pragma unroll
    for (int p = 0; p < 8; p++) bi[p] = (tid & (1u << p)) ? 0xffffffffu : 0u;
    bi[8] = b0; bi[9] = b1; bi[10] = b2; bi[11] = b3; bi[12] = b4;

    // Warp butterfly merge of (cnt desc, row asc), bit-sliced.
#pragma unroll
    for (int k = 1; k < 32; k <<= 1) {
        unsigned o[5], q[13];
#pragma unroll
        for (int p = 0; p < 5; p++)  o[p] = __shfl_xor_sync(0xffffffffu, mx[p], k);
#pragma unroll
        for (int p = 0; p < 13; p++) q[p] = __shfl_xor_sync(0xffffffffu, bi[p], k);
        unsigned gtc = mx[0] & ~o[0];
#pragma unroll
        for (int p = 1; p < 5; p++)
            gtc = (mx[p] & ~o[p]) | (~(mx[p] ^ o[p]) & gtc);
        unsigned orx = 0;
#pragma unroll
        for (int p = 0; p < 5; p++) orx |= mx[p] ^ o[p];    // ~orx = counts equal
        unsigned lt = ~bi[0] & q[0];
#pragma unroll
        for (int p = 1; p < 13; p++)
            lt = (~bi[p] & q[p]) | (~(bi[p] ^ q[p]) & lt);  // my row < partner row
        unsigned tm = gtc | (lt & ~orx);                    // keep mine
#pragma unroll
        for (int p = 0; p < 5; p++)  mx[p] = (mx[p] & tm) | (o[p] & ~tm);
#pragma unroll
        for (int p = 0; p < 13; p++) bi[p] = (bi[p] & tm) | (q[p] & ~tm);
    }

    // lane q extracts query q's (cnt,row) from the merged planes
    unsigned cnt = 0, lr = 0;
#pragma unroll
    for (int p = 0; p < 5; p++)  cnt |= ((mx[p] >> lane) & 1u) << p;
#pragma unroll
    for (int p = 0; p < 8; p++)  lr  |= ((bi[p] >> lane) & 1u) << p;
#pragma unroll
    for (int p = 8; p < 13; p++) lr  |= ((bi[p] >> lane) & 1u) << p;
    // row = tid_part + iter_part*256  (iter bits are bi[8..12])
    unsigned row = rowBase + (lr & 0xFFu) + ((lr >> 8) << 8);
    unsigned key = (cnt << 17) | (131071u - row);
    atomicMax(&g_keys[group * 32 + lane], key);
}

// ---------------------------------------------------------------------------
// Kernel 3: gather meanings of the winner and emit one-hot output.
// Writes ALL out elements (d_out is poisoned).
// ---------------------------------------------------------------------------
__global__ void out_kernel(const void* __restrict__ meanv, float* __restrict__ out) {
    int idx = blockIdx.x * blockDim.x + threadIdx.x;
    if (idx >= BATCH * NTYPES * MPT) return;
    int n = idx / (NTYPES * MPT);
    int r = idx % (NTYPES * MPT);
    int t = r / MPT;
    int c = r % MPT;
    unsigned key = __ldg(&g_keys[n]);
    int row = 131071 - (int)(key & 0x1FFFFu);
    long long mval = g_m64 ? __ldg((const long long*)meanv + (size_t)row * NTYPES + t)
                           : (long long)__ldg((const int*)meanv + (size_t)row * NTYPES + t);
    out[idx] = (mval == (long long)c) ? 1.0f : 0.0f;
}

extern "C" void kernel_launch(void* const* d_in, const int* in_sizes, int n_in,
                              void* d_out, int out_size) {
    const void*  utts     = d_in[0];                 // [16,2048] int64/int32
    const float* support  = (const float*)d_in[1];   // [100000,512] fp32 one-hot
    const void*  meanings = d_in[2];                 // [100000,5] int64/int32
    float* out = (float*)d_out;                      // [2048,5,10] fp32

    decode_kernel<<<(SUPPORT * UTT_LEN + 255) / 256, 256>>>(
        support, (const int*)utts, (const int*)meanings);
    dim3 grid(NS, NGROUPS);
    knn_kernel<<<grid, TPB>>>(utts);
    out_kernel<<<(BATCH * NTYPES * MPT + 127) / 128, 128>>>(meanings, out);
}

// round 3
// speedup vs baseline: 1.8862x; 1.2005x over previous
#include <cuda_runtime.h>

#define VOCAB 32
#define UTT_LEN 16
#define NTYPES 5
#define MPT 10
#define SUPPORT 100000
#define BATCH 2048

#define NS 16                            // support chunks
#define CHUNK (SUPPORT / NS)             // 6250
#define TPB 256
#define FULL_ITERS (CHUNK / TPB)         // 24
#define TAIL (CHUNK - FULL_ITERS * TPB)  // 106
#define NGROUPS (BATCH / 32)             // 64

#define ENTRIES (SUPPORT * UTT_LEN)      // 1,600,000 (divisible by 32)

// scratch (no cudaMalloc allowed)
__device__ unsigned char g_packed[ENTRIES];           // token*4 per position
__device__ unsigned int  g_keys[BATCH];               // (cnt<<17)|(131071-row)
__device__ int g_u64, g_m64;                          // dtype flags

// ---------------------------------------------------------------------------
// Kernel 1 (fused): detect int width + zero keys + decode one-hot support.
// Warp-cooperative, fully coalesced: each warp owns 32 entries = 4KB
// contiguous. Round r: lanes load consecutive float4 (512B/instr = minimal
// 4 wavefronts) covering entries 4r..4r+3; ballots convert one-hot floats
// to bitmasks; lane l extracts the token of entry l.
//   float layout within round: lane L covers entry 4r+(L>>3),
//   vocab 4*(L&7)+comp  =>  submask bit b -> vocab 4*(b&7)+(b>>3).
// ---------------------------------------------------------------------------
__global__ void __launch_bounds__(256) decode_kernel(
        const float* __restrict__ support,
        const int* __restrict__ utts32,
        const int* __restrict__ mean32) {
    const unsigned tid  = blockIdx.x * blockDim.x + threadIdx.x;
    const unsigned lane = threadIdx.x & 31;

    // fused dtype detection (first warp). Values are small non-negative ints;
    // if int64 (LE), every odd 32-bit word of the first 128 pairs is 0.
    if (tid < 32) {
        bool unz = false, mnz = false;
        for (int i = (int)tid; i < 128; i += 32) {
            unz |= (utts32[2 * i + 1] != 0);
            mnz |= (mean32[2 * i + 1] != 0);
        }
        unsigned ub = __ballot_sync(0xffffffffu, unz);
        unsigned mb = __ballot_sync(0xffffffffu, mnz);
        if (tid == 0) { g_u64 = (ub == 0); g_m64 = (mb == 0); }
    }
    if (tid < BATCH) g_keys[tid] = 0u;

    const unsigned gwarp = tid >> 5;              // global warp id
    const unsigned base  = gwarp * 32;            // first entry of this warp
    if (base >= ENTRIES) return;

    const float4* p = reinterpret_cast<const float4*>(support) + (size_t)base * 8;
    const int myr = (int)(lane >> 2);             // round holding my entry
    const int sh  = (int)(lane & 3) * 8;          // byte of my entry in ballots

    unsigned mysub = 0;
#pragma unroll
    for (int r = 0; r < 8; r++) {
        float4 v = __ldcs(p + r * 32 + lane);     // 512B contiguous, streaming
        unsigned bx = __ballot_sync(0xffffffffu, v.x != 0.0f);
        unsigned by = __ballot_sync(0xffffffffu, v.y != 0.0f);
        unsigned bz = __ballot_sync(0xffffffffu, v.z != 0.0f);
        unsigned bw = __ballot_sync(0xffffffffu, v.w != 0.0f);
        unsigned sub = ((bx >> sh) & 0xFFu)
                     | (((by >> sh) & 0xFFu) << 8)
                     | (((bz >> sh) & 0xFFu) << 16)
                     | (((bw >> sh) & 0xFFu) << 24);
        if (r == myr) mysub = sub;
    }
    int b = __ffs(mysub) - 1;                     // bit index in submask
    int v = ((b & 7) << 2) | (b >> 3);            // vocab token
    g_packed[base + lane] = (unsigned char)(v << 2);  // pre-scaled x4
}

// ---------------------------------------------------------------------------
// Kernel 2: bit-sliced match counting + argmax (unchanged from R2 - exact).
// ---------------------------------------------------------------------------
__device__ __forceinline__ void fa(unsigned a, unsigned b, unsigned c,
                                   unsigned& s, unsigned& cy) {
    s  = a ^ b ^ c;                       // LOP3 0x96
    cy = (a & b) | (a & c) | (b & c);     // LOP3 0xE8
}
__device__ __forceinline__ void ha(unsigned a, unsigned b,
                                   unsigned& s, unsigned& cy) {
    s = a ^ b; cy = a & b;
}

__global__ void __launch_bounds__(TPB) knn_kernel(const void* __restrict__ uttsv) {
    __shared__ unsigned tbl[UTT_LEN * VOCAB];  // tbl[m*32+v]: bit q = (query q tok[m]==v)

    const unsigned tid   = threadIdx.x;
    const unsigned lane  = tid & 31;
    const unsigned warp  = tid >> 5;
    const unsigned chunk = blockIdx.x;
    const unsigned group = blockIdx.y;

    // Parallel table build: each of the 8 warps handles 2 positions.
    {
        const int is64 = g_u64;
        const unsigned col = group * 32 + lane;
        const long long* u64p = (const long long*)uttsv;
        const int*       u32p = (const int*)uttsv;
#pragma unroll
        for (int mm = 0; mm < 2; mm++) {
            int m = (int)(warp * 2 + mm);
            int tok = is64 ? (int)u64p[(size_t)m * BATCH + col]
                           : u32p[(size_t)m * BATCH + col];
#pragma unroll
            for (int v = 0; v < VOCAB; v++) {
                unsigned bm = __ballot_sync(0xffffffffu, tok == v);
                if (lane == (unsigned)v) tbl[m * VOCAB + v] = bm;
            }
        }
    }
    __syncthreads();

    const unsigned rowBase = chunk * CHUNK;
    const uint4* pk = reinterpret_cast<const uint4*>(g_packed) + rowBase + tid;
    const char* tbc = (const char*)tbl;

    unsigned mx0 = 0, mx1 = 0, mx2 = 0, mx3 = 0, mx4 = 0;
    unsigned b0 = 0, b1 = 0, b2 = 0, b3 = 0, b4 = 0;

#define STEP(I)                                                                   \
    do {                                                                          \
        uint4 pw = pk[(I) * TPB];                                                 \
        unsigned l0  = *(const unsigned*)(tbc + 0 * 128  + __byte_perm(pw.x, 0, 0x4440)); \
        unsigned l1  = *(const unsigned*)(tbc + 1 * 128  + __byte_perm(pw.x, 0, 0x4441)); \
        unsigned l2  = *(const unsigned*)(tbc + 2 * 128  + __byte_perm(pw.x, 0, 0x4442)); \
        unsigned l3  = *(const unsigned*)(tbc + 3 * 128  + __byte_perm(pw.x, 0, 0x4443)); \
        unsigned l4  = *(const unsigned*)(tbc + 4 * 128  + __byte_perm(pw.y, 0, 0x4440)); \
        unsigned l5  = *(const unsigned*)(tbc + 5 * 128  + __byte_perm(pw.y, 0, 0x4441)); \
        unsigned l6  = *(const unsigned*)(tbc + 6 * 128  + __byte_perm(pw.y, 0, 0x4442)); \
        unsigned l7  = *(const unsigned*)(tbc + 7 * 128  + __byte_perm(pw.y, 0, 0x4443)); \
        unsigned l8  = *(const unsigned*)(tbc + 8 * 128  + __byte_perm(pw.z, 0, 0x4440)); \
        unsigned l9  = *(const unsigned*)(tbc + 9 * 128  + __byte_perm(pw.z, 0, 0x4441)); \
        unsigned l10 = *(const unsigned*)(tbc + 10 * 128 + __byte_perm(pw.z, 0, 0x4442)); \
        unsigned l11 = *(const unsigned*)(tbc + 11 * 128 + __byte_perm(pw.z, 0, 0x4443)); \
        unsigned l12 = *(const unsigned*)(tbc + 12 * 128 + __byte_perm(pw.w, 0, 0x4440)); \
        unsigned l13 = *(const unsigned*)(tbc + 13 * 128 + __byte_perm(pw.w, 0, 0x4441)); \
        unsigned l14 = *(const unsigned*)(tbc + 14 * 128 + __byte_perm(pw.w, 0, 0x4442)); \
        unsigned l15 = *(const unsigned*)(tbc + 15 * 128 + __byte_perm(pw.w, 0, 0x4443)); \
        unsigned s0, c0, s1, c1, s2, c2, s3, c3, s4, c4;                          \
        fa(l0, l1, l2, s0, c0);                                                   \
        fa(l3, l4, l5, s1, c1);                                                   \
        fa(l6, l7, l8, s2, c2);                                                   \
        fa(l9, l10, l11, s3, c3);                                                 \
        fa(l12, l13, l14, s4, c4);                                                \
        unsigned t0, d0, t1, d1;                                                  \
        fa(s0, s1, s2, t0, d0);                                                   \
        fa(s3, s4, l15, t1, d1);                                                  \
        unsigned n0, e0; ha(t0, t1, n0, e0);                                      \
        unsigned f0, g0, f1, g1, f2, g2;                                          \
        fa(c0, c1, c2, f0, g0);                                                   \
        fa(c3, c4, d0, f1, g1);                                                   \
        fa(f0, f1, d1, f2, g2);                                                   \
        unsigned n1, g3; ha(f2, e0, n1, g3);                                      \
        unsigned h0, k0; fa(g0, g1, g2, h0, k0);                                  \
        unsigned n2, k1; ha(h0, g3, n2, k1);                                      \
        unsigned n3, n4; ha(k0, k1, n3, n4);                                      \
        unsigned gt = n0 & ~mx0;                                                  \
        gt = (n1 & ~mx1) | (~(n1 ^ mx1) & gt);                                    \
        gt = (n2 & ~mx2) | (~(n2 ^ mx2) & gt);                                    \
        gt = (n3 & ~mx3) | (~(n3 ^ mx3) & gt);                                    \
        gt = (n4 & ~mx4) | (~(n4 ^ mx4) & gt);                                    \
        mx0 = (n0 & gt) | (mx0 & ~gt);                                            \
        mx1 = (n1 & gt) | (mx1 & ~gt);                                            \
        mx2 = (n2 & gt) | (mx2 & ~gt);                                            \
        mx3 = (n3 & gt) | (mx3 & ~gt);                                            \
        mx4 = (n4 & gt) | (mx4 & ~gt);                                            \
        if ((I) & 1)  b0 |= gt; else b0 &= ~gt;                                   \
        if ((I) & 2)  b1 |= gt; else b1 &= ~gt;                                   \
        if ((I) & 4)  b2 |= gt; else b2 &= ~gt;                                   \
        if ((I) & 8)  b3 |= gt; else b3 &= ~gt;                                   \
        if ((I) & 16) b4 |= gt; else b4 &= ~gt;                                   \
    } while (0)

    STEP(0);  STEP(1);  STEP(2);  STEP(3);  STEP(4);  STEP(5);
    STEP(6);  STEP(7);  STEP(8);  STEP(9);  STEP(10); STEP(11);
    STEP(12); STEP(13); STEP(14); STEP(15); STEP(16); STEP(17);
    STEP(18); STEP(19); STEP(20); STEP(21); STEP(22); STEP(23);
    if (tid < TAIL) STEP(24);
#undef STEP

    // Materialize full row planes: row = tid (8 bits) | iter (5 bits).
    unsigned mx[5] = {mx0, mx1, mx2, mx3, mx4};
    unsigned bi[13];
#pragma unroll
    for (int p = 0; p < 8; p++) bi[p] = (tid & (1u << p)) ? 0xffffffffu : 0u;
    bi[8] = b0; bi[9] = b1; bi[10] = b2; bi[11] = b3; bi[12] = b4;

    // Warp butterfly merge of (cnt desc, row asc), bit-sliced.
#pragma unroll
    for (int k = 1; k < 32; k <<= 1) {
        unsigned o[5], q[13];
#pragma unroll
        for (int p = 0; p < 5; p++)  o[p] = __shfl_xor_sync(0xffffffffu, mx[p], k);
#pragma unroll
        for (int p = 0; p < 13; p++) q[p] = __shfl_xor_sync(0xffffffffu, bi[p], k);
        unsigned gtc = mx[0] & ~o[0];
#pragma unroll
        for (int p = 1; p < 5; p++)
            gtc = (mx[p] & ~o[p]) | (~(mx[p] ^ o[p]) & gtc);
        unsigned orx = 0;
#pragma unroll
        for (int p = 0; p < 5; p++) orx |= mx[p] ^ o[p];    // ~orx = counts equal
        unsigned lt = ~bi[0] & q[0];
#pragma unroll
        for (int p = 1; p < 13; p++)
            lt = (~bi[p] & q[p]) | (~(bi[p] ^ q[p]) & lt);  // my row < partner row
        unsigned tm = gtc | (lt & ~orx);                    // keep mine
#pragma unroll
        for (int p = 0; p < 5; p++)  mx[p] = (mx[p] & tm) | (o[p] & ~tm);
#pragma unroll
        for (int p = 0; p < 13; p++) bi[p] = (bi[p] & tm) | (q[p] & ~tm);
    }

    // lane q extracts query q's (cnt,row) from the merged planes
    unsigned cnt = 0, lr = 0;
#pragma unroll
    for (int p = 0; p < 5; p++)  cnt |= ((mx[p] >> lane) & 1u) << p;
#pragma unroll
    for (int p = 0; p < 13; p++) lr  |= ((bi[p] >> lane) & 1u) << p;
    unsigned row = rowBase + lr;
    unsigned key = (cnt << 17) | (131071u - row);
    atomicMax(&g_keys[group * 32 + lane], key);
}

// ---------------------------------------------------------------------------
// Kernel 3: gather meanings of the winner and emit one-hot output.
// ---------------------------------------------------------------------------
__global__ void out_kernel(const void* __restrict__ meanv, float* __restrict__ out) {
    int idx = blockIdx.x * blockDim.x + threadIdx.x;
    if (idx >= BATCH * NTYPES * MPT) return;
    int n = idx / (NTYPES * MPT);
    int r = idx % (NTYPES * MPT);
    int t = r / MPT;
    int c = r % MPT;
    unsigned key = __ldg(&g_keys[n]);
    int row = 131071 - (int)(key & 0x1FFFFu);
    long long mval = g_m64 ? __ldg((const long long*)meanv + (size_t)row * NTYPES + t)
                           : (long long)__ldg((const int*)meanv + (size_t)row * NTYPES + t);
    out[idx] = (mval == (long long)c) ? 1.0f : 0.0f;
}

extern "C" void kernel_launch(void* const* d_in, const int* in_sizes, int n_in,
                              void* d_out, int out_size) {
    const void*  utts     = d_in[0];                 // [16,2048] int64/int32
    const float* support  = (const float*)d_in[1];   // [100000,512] fp32 one-hot
    const void*  meanings = d_in[2];                 // [100000,5] int64/int32
    float* out = (float*)d_out;                      // [2048,5,10] fp32

    // one warp per 32 entries: 1.6M entries -> 50000 warps -> 6250 blocks
    decode_kernel<<<(ENTRIES / 32 + 7) / 8, 256>>>(
        support, (const int*)utts, (const int*)meanings);
    dim3 grid(NS, NGROUPS);
    knn_kernel<<<grid, TPB>>>(utts);
    out_kernel<<<(BATCH * NTYPES * MPT + 127) / 128, 128>>>(meanings, out);
}